// round 2
// baseline (speedup 1.0000x reference)
#include <cuda_runtime.h>
#include <cuda_bf16.h>
#include <math.h>

// ---------------- problem constants ----------------
#define BATCH   32
#define DMODEL  1024
#define LSEQ    256
#define MROWS   (BATCH * LSEQ)     // 8192
#define NLAYERS 6
#define NHEADS  16
#define HDIM    64

// ---------------- scratch (device globals; no allocations allowed) ---------
__device__ float g_Xp[MROWS * DMODEL];          // patchified input
__device__ float g_h[MROWS * DMODEL];           // residual stream
__device__ float g_tmp[MROWS * DMODEL];         // ln/modulate output
__device__ float g_qkv[MROWS * 3 * DMODEL];     // qkv projections
__device__ float g_attn[MROWS * DMODEL];        // attention output
__device__ float g_hidden[MROWS * 4 * DMODEL];  // mlp hidden
__device__ float g_te[BATCH * DMODEL];
__device__ float g_t1[BATCH * DMODEL];
__device__ float g_temb[BATCH * DMODEL];
__device__ float g_cond[BATCH * DMODEL];
__device__ float g_scond[BATCH * DMODEL];
__device__ float g_mods[BATCH * 6 * DMODEL];
__device__ float g_fmods[BATCH * 2 * DMODEL];

__device__ __forceinline__ float silu_f(float x) {
    return x / (1.0f + __expf(-x));
}

// ---------------- patchify: [B,C,H,W] -> [B*L, 1024] ----------------------
__global__ void patchify_kernel(const float* __restrict__ x, float* __restrict__ Xp) {
    int o = blockIdx.x * blockDim.x + threadIdx.x;
    if (o >= MROWS * DMODEL) return;
    int d = o & 1023;
    int l = (o >> 10) & 255;
    int b = o >> 18;
    int c  = d >> 8;
    int ph = (d >> 4) & 15;
    int pw = d & 15;
    int gh = l >> 4;
    int gw = l & 15;
    Xp[o] = x[(((b * 4 + c) * 256 + gh * 16 + ph) << 8) + gw * 16 + pw];
}

// ---------------- unpatchify: [B*L,1024] -> [B,C,H,W] ----------------------
__global__ void unpatchify_kernel(const float* __restrict__ hf, float* __restrict__ out) {
    int o = blockIdx.x * blockDim.x + threadIdx.x;
    if (o >= MROWS * DMODEL) return;
    int W = o & 255;
    int H = (o >> 8) & 255;
    int c = (o >> 16) & 3;
    int b = o >> 18;
    int gh = H >> 4, ph = H & 15;
    int gw = W >> 4, pw = W & 15;
    out[o] = hf[((b * 256 + gh * 16 + gw) << 10) + c * 256 + ph * 16 + pw];
}

// ---------------- main GEMM: C[M,N] = A[M,K] @ B[K,N] (+epilogue) ----------
// BM=128, BN=64, BK=16, 256 threads, 8x4 per-thread microtile.
// MODE 0: C = acc + bias
// MODE 1: C = silu(acc + bias)
// MODE 2: C = res + gate[b] * (acc + bias)     (b = row >> 8)
template <int MODE>
__global__ void gemm128x64(const float* __restrict__ A, const float* __restrict__ B,
                           const float* __restrict__ bias, float* __restrict__ C,
                           const float* __restrict__ res, const float* __restrict__ gate,
                           int N, int K, int gstride) {
    __shared__ __align__(16) float As[16][132];   // padded, transposed
    __shared__ __align__(16) float Bs[16][64];

    const int tid = threadIdx.x;
    const int row_base = blockIdx.y * 128;
    const int col_base = blockIdx.x * 64;
    const int ty = tid >> 4;     // 0..15 -> 8 rows each
    const int tx = tid & 15;     // 0..15 -> 4 cols each

    float acc[8][4];
#pragma unroll
    for (int i = 0; i < 8; i++)
#pragma unroll
        for (int j = 0; j < 4; j++) acc[i][j] = 0.0f;

    for (int k0 = 0; k0 < K; k0 += 16) {
        // load A tile (128x16) transposed into As[k][row]
#pragma unroll
        for (int i = 0; i < 2; i++) {
            int idx = tid * 2 + i;          // 0..511 float4 slots
            int r = idx >> 2;               // 0..127
            int kc = (idx & 3) * 4;         // 0,4,8,12
            float4 v = *(const float4*)&A[(size_t)(row_base + r) * K + k0 + kc];
            As[kc + 0][r] = v.x;
            As[kc + 1][r] = v.y;
            As[kc + 2][r] = v.z;
            As[kc + 3][r] = v.w;
        }
        // load B tile (16x64)
        {
            int r = tid >> 4;
            int c = (tid & 15) * 4;
            *(float4*)&Bs[r][c] = *(const float4*)&B[(size_t)(k0 + r) * N + col_base + c];
        }
        __syncthreads();

#pragma unroll
        for (int kk = 0; kk < 16; kk++) {
            float4 a0 = *(const float4*)&As[kk][ty * 8];
            float4 a1 = *(const float4*)&As[kk][ty * 8 + 4];
            float4 bv = *(const float4*)&Bs[kk][tx * 4];
            float a[8] = {a0.x, a0.y, a0.z, a0.w, a1.x, a1.y, a1.z, a1.w};
            float bb[4] = {bv.x, bv.y, bv.z, bv.w};
#pragma unroll
            for (int i = 0; i < 8; i++)
#pragma unroll
                for (int j = 0; j < 4; j++) acc[i][j] = fmaf(a[i], bb[j], acc[i][j]);
        }
        __syncthreads();
    }

#pragma unroll
    for (int i = 0; i < 8; i++) {
        int row = row_base + ty * 8 + i;
        int bidx = row >> 8;
#pragma unroll
        for (int j = 0; j < 4; j++) {
            int col = col_base + tx * 4 + j;
            float v = acc[i][j] + bias[col];
            if (MODE == 1) v = silu_f(v);
            if (MODE == 2) v = res[(size_t)row * N + col] + gate[(size_t)bidx * gstride + col] * v;
            C[(size_t)row * N + col] = v;
        }
    }
}

// ---------------- small-M GEMM (M=32): C[32,N] = A[32,K] @ B[K,N] ----------
// mode 0: +bias, mode 1: silu(+bias)
__global__ void gemm_small32(const float* __restrict__ A, const float* __restrict__ B,
                             const float* __restrict__ bias, float* __restrict__ C,
                             int K, int N, int mode) {
    __shared__ __align__(16) float As[32][128];
    const int tid = threadIdx.x;
    const int col = blockIdx.x * 64 + (tid & 63);
    const int rg = tid >> 6;   // 0..3 -> 8 rows each

    float acc[8];
#pragma unroll
    for (int r = 0; r < 8; r++) acc[r] = 0.0f;

    for (int k0 = 0; k0 < K; k0 += 128) {
#pragma unroll
        for (int t = 0; t < 4; t++) {
            int fid = t * 256 + tid;       // 1024 float4 slots
            int r = fid >> 5;
            int kc = (fid & 31) * 4;
            *(float4*)&As[r][kc] = *(const float4*)&A[(size_t)r * K + k0 + kc];
        }
        __syncthreads();
        for (int k = 0; k < 128; k++) {
            float bv = B[(size_t)(k0 + k) * N + col];
#pragma unroll
            for (int r = 0; r < 8; r++) acc[r] = fmaf(As[rg * 8 + r][k], bv, acc[r]);
        }
        __syncthreads();
    }
#pragma unroll
    for (int r = 0; r < 8; r++) {
        float v = acc[r] + bias[col];
        if (mode == 1) v = silu_f(v);
        C[(size_t)(rg * 8 + r) * N + col] = v;
    }
}

// ---------------- LayerNorm + modulate ------------------------------------
// Y[row,:] = ln(X[row,:]) * (1 + s[b,:]) + bmod[b,:]
__global__ void ln_mod_kernel(const float* __restrict__ X, const float* __restrict__ s_ptr,
                              const float* __restrict__ b_ptr, int mstride,
                              float* __restrict__ Y) {
    const int row = blockIdx.x;
    const int b = row >> 8;
    const int tid = threadIdx.x;
    const float* xr = X + (size_t)row * DMODEL;

    float4 v = *(const float4*)&xr[tid * 4];
    float s = v.x + v.y + v.z + v.w;
    float ss = v.x * v.x + v.y * v.y + v.z * v.z + v.w * v.w;
#pragma unroll
    for (int o = 16; o > 0; o >>= 1) {
        s += __shfl_down_sync(0xffffffffu, s, o);
        ss += __shfl_down_sync(0xffffffffu, ss, o);
    }
    __shared__ float rs[8], rss[8], stats[2];
    int wid = tid >> 5, lane = tid & 31;
    if (lane == 0) { rs[wid] = s; rss[wid] = ss; }
    __syncthreads();
    if (tid == 0) {
        float S = 0.0f, SS = 0.0f;
#pragma unroll
        for (int w = 0; w < 8; w++) { S += rs[w]; SS += rss[w]; }
        float mean = S * (1.0f / DMODEL);
        float var = SS * (1.0f / DMODEL) - mean * mean;
        stats[0] = mean;
        stats[1] = rsqrtf(var + 1e-5f);
    }
    __syncthreads();
    float mean = stats[0], rstd = stats[1];
    const float* sp = s_ptr + (size_t)b * mstride;
    const float* bp = b_ptr + (size_t)b * mstride;
    float xv[4] = {v.x, v.y, v.z, v.w};
    float4 outv;
    float* op = &outv.x;
#pragma unroll
    for (int j = 0; j < 4; j++) {
        int col = tid * 4 + j;
        op[j] = (xv[j] - mean) * rstd * (1.0f + sp[col]) + bp[col];
    }
    *(float4*)&Y[(size_t)row * DMODEL + tid * 4] = outv;
}

// ---------------- attention: one block per (b, head) -----------------------
// 256 threads; thread i = query row i. K,V in dynamic smem (128 KB).
__global__ void attn_kernel(const float* __restrict__ qkv, float* __restrict__ out) {
    extern __shared__ float sm[];
    float* Ks = sm;                 // [256][64]
    float* Vs = sm + 256 * 64;      // [256][64]

    const int bh = blockIdx.x;
    const int b = bh >> 4;
    const int h = bh & 15;
    const int tid = threadIdx.x;
    const float* base = qkv + (size_t)b * LSEQ * 3 * DMODEL;

    // cooperative K,V load: 16 threads per row (coalesced 256B per row)
#pragma unroll
    for (int it = 0; it < 16; it++) {
        int idx = it * 256 + tid;          // 0..4095 float4 slots
        int row = idx >> 4;
        int dc = (idx & 15) * 4;
        *(float4*)&Ks[row * 64 + dc] =
            *(const float4*)&base[(size_t)row * 3072 + DMODEL + h * 64 + dc];
        *(float4*)&Vs[row * 64 + dc] =
            *(const float4*)&base[(size_t)row * 3072 + 2 * DMODEL + h * 64 + dc];
    }
    __syncthreads();

    const int i = tid;
    float q[HDIM];
#pragma unroll
    for (int d = 0; d < HDIM; d += 4) {
        float4 t = *(const float4*)&base[(size_t)i * 3072 + h * 64 + d];
        q[d] = t.x; q[d + 1] = t.y; q[d + 2] = t.z; q[d + 3] = t.w;
    }

    float m = -1e30f, ssum = 0.0f;
    float o[HDIM];
#pragma unroll
    for (int d = 0; d < HDIM; d++) o[d] = 0.0f;

    for (int j = 0; j < LSEQ; j++) {
        const float* kj = &Ks[j * 64];
        float sc = 0.0f;
#pragma unroll
        for (int d = 0; d < HDIM; d++) sc = fmaf(q[d], kj[d], sc);
        sc *= 0.125f;  // HD^-0.5
        float nm = fmaxf(m, sc);
        float f = __expf(m - nm);
        float p = __expf(sc - nm);
        ssum = ssum * f + p;
        const float* vj = &Vs[j * 64];
#pragma unroll
        for (int d = 0; d < HDIM; d++) o[d] = fmaf(o[d], f, p * vj[d]);
        m = nm;
    }
    float inv = 1.0f / ssum;
    float* op = &out[(size_t)(b * LSEQ + i) * DMODEL + h * 64];
#pragma unroll
    for (int d = 0; d < HDIM; d += 4) {
        float4 t = make_float4(o[d] * inv, o[d + 1] * inv, o[d + 2] * inv, o[d + 3] * inv);
        *(float4*)&op[d] = t;
    }
}

// ---------------- timestep embedding --------------------------------------
__global__ void te_kernel(const int* __restrict__ t, float* __restrict__ te) {
    int idx = blockIdx.x * blockDim.x + threadIdx.x;
    if (idx >= BATCH * DMODEL) return;
    int b = idx >> 10;
    int d = idx & 1023;
    int i = (d < 512) ? d : d - 512;
    float ang = powf(10000.0f, -((float)i) / 512.0f);
    float a = (float)t[b] * ang;
    te[idx] = (d < 512) ? sinf(a) : cosf(a);
}

// ---------------- cond = y_table[y] + temb; scond = silu(cond) -------------
__global__ void cond_kernel(const int* __restrict__ y, const float* __restrict__ ytab,
                            const float* __restrict__ temb, float* __restrict__ cond,
                            float* __restrict__ scond) {
    int idx = blockIdx.x * blockDim.x + threadIdx.x;
    if (idx >= BATCH * DMODEL) return;
    int b = idx >> 10;
    int d = idx & 1023;
    float c = ytab[(size_t)y[b] * DMODEL + d] + temb[idx];
    cond[idx] = c;
    scond[idx] = silu_f(c);
}

// ---------------- launch ----------------------------------------------------
extern "C" void kernel_launch(void* const* d_in, const int* in_sizes, int n_in,
                              void* d_out, int out_size) {
    const float* x        = (const float*)d_in[0];
    const int*   y        = (const int*)d_in[1];
    const int*   t        = (const int*)d_in[2];
    const float* xw       = (const float*)d_in[3];
    const float* xb       = (const float*)d_in[4];
    // d_in[5] = pos_embed (unused by the reference forward)
    const float* ytab     = (const float*)d_in[6];
    const float* t_w1     = (const float*)d_in[7];
    const float* t_b1     = (const float*)d_in[8];
    const float* t_w2     = (const float*)d_in[9];
    const float* t_b2     = (const float*)d_in[10];
    const float* qkv_w    = (const float*)d_in[11];
    const float* qkv_b    = (const float*)d_in[12];
    const float* proj_w   = (const float*)d_in[13];
    const float* proj_b   = (const float*)d_in[14];
    const float* mlp_w1   = (const float*)d_in[15];
    const float* mlp_b1   = (const float*)d_in[16];
    const float* mlp_w2   = (const float*)d_in[17];
    const float* mlp_b2   = (const float*)d_in[18];
    const float* cond_w   = (const float*)d_in[19];
    const float* cond_b   = (const float*)d_in[20];
    const float* final_w  = (const float*)d_in[21];
    const float* final_b  = (const float*)d_in[22];
    float* outp = (float*)d_out;

    float *Xp, *h, *tmp, *qkvb, *attnb, *hidden, *te, *t1, *temb, *cond, *scond, *mods, *fmods;
    cudaGetSymbolAddress((void**)&Xp, g_Xp);
    cudaGetSymbolAddress((void**)&h, g_h);
    cudaGetSymbolAddress((void**)&tmp, g_tmp);
    cudaGetSymbolAddress((void**)&qkvb, g_qkv);
    cudaGetSymbolAddress((void**)&attnb, g_attn);
    cudaGetSymbolAddress((void**)&hidden, g_hidden);
    cudaGetSymbolAddress((void**)&te, g_te);
    cudaGetSymbolAddress((void**)&t1, g_t1);
    cudaGetSymbolAddress((void**)&temb, g_temb);
    cudaGetSymbolAddress((void**)&cond, g_cond);
    cudaGetSymbolAddress((void**)&scond, g_scond);
    cudaGetSymbolAddress((void**)&mods, g_mods);
    cudaGetSymbolAddress((void**)&fmods, g_fmods);

    cudaFuncSetAttribute(attn_kernel, cudaFuncAttributeMaxDynamicSharedMemorySize, 131072);

    const int D = DMODEL;

    // stem: patchify + embed
    patchify_kernel<<<(MROWS * D) / 256, 256>>>(x, Xp);
    gemm128x64<0><<<dim3(D / 64, MROWS / 128), 256>>>(Xp, xw, xb, h, nullptr, nullptr, D, D, 0);

    // cond path
    te_kernel<<<(BATCH * D) / 256, 256>>>(t, te);
    gemm_small32<<<D / 64, 256>>>(te, t_w1, t_b1, t1, D, D, 1);
    gemm_small32<<<D / 64, 256>>>(t1, t_w2, t_b2, temb, D, D, 0);
    cond_kernel<<<(BATCH * D) / 256, 256>>>(y, ytab, temb, cond, scond);

    for (int l = 0; l < NLAYERS; l++) {
        const float* cwl  = cond_w  + (size_t)l * D * 6 * D;
        const float* cbl  = cond_b  + (size_t)l * 6 * D;
        const float* qwl  = qkv_w   + (size_t)l * D * 3 * D;
        const float* qbl  = qkv_b   + (size_t)l * 3 * D;
        const float* pwl  = proj_w  + (size_t)l * D * D;
        const float* pbl  = proj_b  + (size_t)l * D;
        const float* w1l  = mlp_w1  + (size_t)l * D * 4 * D;
        const float* b1l  = mlp_b1  + (size_t)l * 4 * D;
        const float* w2l  = mlp_w2  + (size_t)l * 4 * D * D;
        const float* b2l  = mlp_b2  + (size_t)l * D;

        // mods = scond @ cond_w + cond_b  : [32, 6144]
        gemm_small32<<<(6 * D) / 64, 256>>>(scond, cwl, cbl, mods, D, 6 * D, 0);

        // attention branch
        ln_mod_kernel<<<MROWS, 256>>>(h, mods + 0, mods + D, 6 * D, tmp);
        gemm128x64<0><<<dim3((3 * D) / 64, MROWS / 128), 256>>>(tmp, qwl, qbl, qkvb,
                                                                nullptr, nullptr, 3 * D, D, 0);
        attn_kernel<<<BATCH * NHEADS, 256, 131072>>>(qkvb, attnb);
        gemm128x64<2><<<dim3(D / 64, MROWS / 128), 256>>>(attnb, pwl, pbl, h,
                                                          h, mods + 2 * D, D, D, 6 * D);

        // mlp branch
        ln_mod_kernel<<<MROWS, 256>>>(h, mods + 3 * D, mods + 4 * D, 6 * D, tmp);
        gemm128x64<1><<<dim3((4 * D) / 64, MROWS / 128), 256>>>(tmp, w1l, b1l, hidden,
                                                                nullptr, nullptr, 4 * D, D, 0);
        gemm128x64<2><<<dim3(D / 64, MROWS / 128), 256>>>(hidden, w2l, b2l, h,
                                                          h, mods + 5 * D, D, 4 * D, 6 * D);
    }

    // final modulation + unpatchify
    gemm_small32<<<(2 * D) / 64, 256>>>(cond, final_w, final_b, fmods, D, 2 * D, 0);
    ln_mod_kernel<<<MROWS, 256>>>(h, fmods + 0, fmods + D, 2 * D, tmp);
    unpatchify_kernel<<<(MROWS * D) / 256, 256>>>(tmp, outp);
}

// round 4
// speedup vs baseline: 2.2176x; 2.2176x over previous
#include <cuda_runtime.h>
#include <cuda_bf16.h>
#include <cstdint>
#include <math.h>

// ---------------- problem constants ----------------
#define BATCH   32
#define DMODEL  1024
#define LSEQ    256
#define MROWS   (BATCH * LSEQ)     // 8192
#define NLAYERS 6
#define NHEADS  16
#define HDIM    64

// ---------------- device scratch (no allocations allowed) -------------------
__device__ __nv_bfloat16 g_XpH[MROWS * DMODEL];
__device__ __nv_bfloat16 g_XpL[MROWS * DMODEL];
__device__ float         g_h  [MROWS * DMODEL];
__device__ __nv_bfloat16 g_tH [MROWS * DMODEL];
__device__ __nv_bfloat16 g_tL [MROWS * DMODEL];
__device__ float         g_qkv[MROWS * 3 * DMODEL];
__device__ __nv_bfloat16 g_aH [MROWS * DMODEL];
__device__ __nv_bfloat16 g_aL [MROWS * DMODEL];
__device__ __nv_bfloat16 g_hidH[MROWS * 4 * DMODEL];
__device__ __nv_bfloat16 g_hidL[MROWS * 4 * DMODEL];
// transposed + split weights (per layer, reused)
__device__ __nv_bfloat16 g_WeH[DMODEL * DMODEL],     g_WeL[DMODEL * DMODEL];
__device__ __nv_bfloat16 g_WqH[3 * DMODEL * DMODEL], g_WqL[3 * DMODEL * DMODEL];
__device__ __nv_bfloat16 g_WpH[DMODEL * DMODEL],     g_WpL[DMODEL * DMODEL];
__device__ __nv_bfloat16 g_W1H[4 * DMODEL * DMODEL], g_W1L[4 * DMODEL * DMODEL];
__device__ __nv_bfloat16 g_W2H[4 * DMODEL * DMODEL], g_W2L[4 * DMODEL * DMODEL];
// cond path fp32
__device__ float g_te[BATCH * DMODEL];
__device__ float g_t1[BATCH * DMODEL];
__device__ float g_temb[BATCH * DMODEL];
__device__ float g_cond[BATCH * DMODEL];
__device__ float g_scond[BATCH * DMODEL];
__device__ float g_mods[BATCH * 6 * DMODEL];
__device__ float g_fmods[BATCH * 2 * DMODEL];

__device__ __forceinline__ float silu_f(float x) { return x / (1.0f + __expf(-x)); }

// ---------------- PTX helpers (portable: sm_80/90 baseline only) ------------
__device__ __forceinline__ uint32_t smem_u32(const void* p) {
    uint32_t a;
    asm("{ .reg .u64 t; cvta.to.shared.u64 t, %1; cvt.u32.u64 %0, t; }" : "=r"(a) : "l"(p));
    return a;
}
#define CP_COMMIT() asm volatile("cp.async.commit_group;" ::: "memory")
#define CP_WAIT(n)  asm volatile("cp.async.wait_group %0;" :: "n"(n) : "memory")
__device__ __forceinline__ void cp16(uint32_t dst, const void* src) {
    asm volatile("cp.async.cg.shared.global [%0], [%1], 16;" :: "r"(dst), "l"(src));
}
#define LDSM4(r, addr) \
    asm volatile("ldmatrix.sync.aligned.m8n8.x4.shared.b16 {%0,%1,%2,%3}, [%4];" \
        : "=r"((r)[0]), "=r"((r)[1]), "=r"((r)[2]), "=r"((r)[3]) : "r"(addr))
#define MMA_BF16(d, a, b0, b1) \
    asm volatile("mma.sync.aligned.m16n8k16.row.col.f32.bf16.bf16.f32 " \
        "{%0,%1,%2,%3}, {%4,%5,%6,%7}, {%8,%9}, {%0,%1,%2,%3};" \
        : "+f"((d)[0]), "+f"((d)[1]), "+f"((d)[2]), "+f"((d)[3]) \
        : "r"((a)[0]), "r"((a)[1]), "r"((a)[2]), "r"((a)[3]), "r"(b0), "r"(b1))

// split-precision helper
__device__ __forceinline__ void store4_hl(__nv_bfloat16* __restrict__ H,
                                          __nv_bfloat16* __restrict__ L, size_t idx,
                                          float v0, float v1, float v2, float v3) {
    __nv_bfloat16 h0 = __float2bfloat16(v0), h1 = __float2bfloat16(v1);
    __nv_bfloat16 h2 = __float2bfloat16(v2), h3 = __float2bfloat16(v3);
    __nv_bfloat162 a, b; a.x = h0; a.y = h1; b.x = h2; b.y = h3;
    *(__nv_bfloat162*)(H + idx) = a; *(__nv_bfloat162*)(H + idx + 2) = b;
    __nv_bfloat162 c, d;
    c.x = __float2bfloat16(v0 - __bfloat162float(h0));
    c.y = __float2bfloat16(v1 - __bfloat162float(h1));
    d.x = __float2bfloat16(v2 - __bfloat162float(h2));
    d.y = __float2bfloat16(v3 - __bfloat162float(h3));
    *(__nv_bfloat162*)(L + idx) = c; *(__nv_bfloat162*)(L + idx + 2) = d;
}

// ---------------- smem tile swizzle ----------------------------------------
// tile layout: [rows][32 bf16] = rows of 64B = 4 x 16B units.
// physical unit = u ^ ((r>>1)&3): 8 ldmatrix rows -> 8 distinct 16B bank groups.
__device__ __forceinline__ uint32_t swz(int r, int u) {
    return (uint32_t)(r * 64 + ((u ^ ((r >> 1) & 3)) << 4));
}
__device__ __forceinline__ void load_tile(uint32_t dst, const __nv_bfloat16* __restrict__ src,
                                          int row0, int K, int k0, int tid) {
#pragma unroll
    for (int ii = 0; ii < 2; ii++) {
        int i = tid + ii * 256;        // 0..511 : 128 rows x 4 units
        int r = i >> 2, u = i & 3;
        cp16(dst + swz(r, u), src + (size_t)(row0 + r) * K + k0 + u * 8);
    }
}

// ---------------- tensor-core GEMM via mma.sync ------------------------------
// C[M,N] = A[M,K] @ W[K,N]; A as (Ah+Al) bf16 [M,K]; W as (Bh+Bl) bf16 [N,K] (transposed).
// acc = Ah*Bh + Al*Bh + Ah*Bl  (fp32 accum)
// MODE 0: Cf = acc + bias
// MODE 1: (Chi,Clo) = split(silu(acc + bias))
// MODE 2: Cf = res + gate[row>>8]*(acc + bias)
#define S_AH 0u
#define S_AL 8192u
#define S_BH 16384u
#define S_BL 24576u
#define STAGE_B 32768u
#define GEMM_SMEM 65536

template <int MODE>
__global__ void __launch_bounds__(256)
gemm_mma(const __nv_bfloat16* __restrict__ Ah, const __nv_bfloat16* __restrict__ Al,
         const __nv_bfloat16* __restrict__ Bh, const __nv_bfloat16* __restrict__ Bl,
         const float* __restrict__ bias, float* __restrict__ Cf,
         __nv_bfloat16* __restrict__ Chi, __nv_bfloat16* __restrict__ Clo,
         const float* __restrict__ res, const float* __restrict__ gate, int gstride,
         int N, int K) {
    extern __shared__ __align__(128) char smem[];
    const uint32_t sb = smem_u32(smem);
    const int tid = threadIdx.x;
    const int w = tid >> 5, lane = tid & 31;
    const int wm = w >> 2, wn = w & 3;            // 2 x 4 warp grid, warp tile 64x32
    const int row_base = blockIdx.y * 128;
    const int col_base = blockIdx.x * 128;

    float acc[4][4][4];
#pragma unroll
    for (int i = 0; i < 4; i++)
#pragma unroll
        for (int j = 0; j < 4; j++)
#pragma unroll
            for (int q = 0; q < 4; q++) acc[i][j][q] = 0.0f;

    const int nc = K / 32;
    // prefetch chunk 0 into stage 0
    load_tile(sb + S_AH, Ah, row_base, K, 0, tid);
    load_tile(sb + S_AL, Al, row_base, K, 0, tid);
    load_tile(sb + S_BH, Bh, col_base, K, 0, tid);
    load_tile(sb + S_BL, Bl, col_base, K, 0, tid);
    CP_COMMIT();

    // per-thread ldmatrix address pieces
    const int li = lane >> 3;                       // matrix index 0..3
    const int a_row = ((li & 1) << 3) + (lane & 7); // A: m0: r0-7/u0, m1: r8-15/u0, m2: r0-7/u1, m3: r8-15/u1
    const int a_us  = li >> 1;
    const int b_row = ((li >> 1) << 3) + (lane & 7);// B: m0: n0-7/u0, m1: n0-7/u1, m2: n8-15/u0, m3: n8-15/u1
    const int b_us  = li & 1;

    for (int c = 0; c < nc; c++) {
        const uint32_t st = sb + (uint32_t)(c & 1) * STAGE_B;
        if (c + 1 < nc) {
            const uint32_t st2 = sb + (uint32_t)((c + 1) & 1) * STAGE_B;
            const int k0 = (c + 1) * 32;
            load_tile(st2 + S_AH, Ah, row_base, K, k0, tid);
            load_tile(st2 + S_AL, Al, row_base, K, k0, tid);
            load_tile(st2 + S_BH, Bh, col_base, K, k0, tid);
            load_tile(st2 + S_BL, Bl, col_base, K, k0, tid);
            CP_COMMIT();
            CP_WAIT(1);
        } else {
            CP_WAIT(0);
        }
        __syncthreads();

#pragma unroll
        for (int kk = 0; kk < 2; kk++) {
            uint32_t ah[4][4], al[4][4], bh[2][4], bl[2][4];
#pragma unroll
            for (int mt = 0; mt < 4; mt++) {
                const int r = wm * 64 + mt * 16 + a_row;
                const int u = kk * 2 + a_us;
                LDSM4(ah[mt], st + S_AH + swz(r, u));
                LDSM4(al[mt], st + S_AL + swz(r, u));
            }
#pragma unroll
            for (int p = 0; p < 2; p++) {
                const int r = wn * 32 + p * 16 + b_row;
                const int u = kk * 2 + b_us;
                LDSM4(bh[p], st + S_BH + swz(r, u));
                LDSM4(bl[p], st + S_BL + swz(r, u));
            }
#pragma unroll
            for (int mt = 0; mt < 4; mt++) {
#pragma unroll
                for (int nt = 0; nt < 4; nt++) {
                    const uint32_t* fh = &bh[nt >> 1][(nt & 1) * 2];
                    const uint32_t* fl = &bl[nt >> 1][(nt & 1) * 2];
                    MMA_BF16(acc[mt][nt], ah[mt], fh[0], fh[1]);
                    MMA_BF16(acc[mt][nt], al[mt], fh[0], fh[1]);
                    MMA_BF16(acc[mt][nt], ah[mt], fl[0], fl[1]);
                }
            }
        }
        __syncthreads();
    }

    // epilogue (accumulators in registers)
#pragma unroll
    for (int mt = 0; mt < 4; mt++) {
        const int r0 = row_base + wm * 64 + mt * 16 + (lane >> 2);
#pragma unroll
        for (int rr = 0; rr < 2; rr++) {
            const int row = r0 + rr * 8;
            const int bidx = row >> 8;
#pragma unroll
            for (int nt = 0; nt < 4; nt++) {
                const int col = col_base + wn * 32 + nt * 8 + (lane & 3) * 2;
                float v0 = acc[mt][nt][rr * 2 + 0] + bias[col];
                float v1 = acc[mt][nt][rr * 2 + 1] + bias[col + 1];
                if (MODE == 1) {
                    v0 = silu_f(v0); v1 = silu_f(v1);
                    __nv_bfloat16 h0 = __float2bfloat16(v0), h1 = __float2bfloat16(v1);
                    __nv_bfloat162 hh; hh.x = h0; hh.y = h1;
                    *(__nv_bfloat162*)&Chi[(size_t)row * N + col] = hh;
                    __nv_bfloat162 ll;
                    ll.x = __float2bfloat16(v0 - __bfloat162float(h0));
                    ll.y = __float2bfloat16(v1 - __bfloat162float(h1));
                    *(__nv_bfloat162*)&Clo[(size_t)row * N + col] = ll;
                } else {
                    if (MODE == 2) {
                        float2 g = *(const float2*)&gate[(size_t)bidx * gstride + col];
                        float2 rv = *(const float2*)&res[(size_t)row * N + col];
                        v0 = rv.x + g.x * v0;
                        v1 = rv.y + g.y * v1;
                    }
                    *(float2*)&Cf[(size_t)row * N + col] = make_float2(v0, v1);
                }
            }
        }
    }
}

// ---------------- weight transpose + bf16 split: W[K,N] -> T[N,K] ----------
__global__ void transpose_split(const float* __restrict__ W, __nv_bfloat16* __restrict__ Th,
                                __nv_bfloat16* __restrict__ Tl, int K, int N) {
    __shared__ float tile[32][33];
    const int kb = blockIdx.y * 32, nb = blockIdx.x * 32;
    const int tx = threadIdx.x, ty = threadIdx.y;  // 32x8
#pragma unroll
    for (int i = 0; i < 32; i += 8)
        tile[ty + i][tx] = W[(size_t)(kb + ty + i) * N + nb + tx];
    __syncthreads();
#pragma unroll
    for (int i = 0; i < 32; i += 8) {
        float v = tile[tx][ty + i];  // = W[kb+tx][nb+ty+i]
        __nv_bfloat16 h = __float2bfloat16(v);
        size_t o = (size_t)(nb + ty + i) * K + kb + tx;
        Th[o] = h;
        Tl[o] = __float2bfloat16(v - __bfloat162float(h));
    }
}

// ---------------- patchify -> bf16 split ------------------------------------
__global__ void patchify_kernel(const float* __restrict__ x, __nv_bfloat16* __restrict__ H,
                                __nv_bfloat16* __restrict__ L) {
    int o = blockIdx.x * blockDim.x + threadIdx.x;
    if (o >= MROWS * DMODEL) return;
    int d = o & 1023, l = (o >> 10) & 255, b = o >> 18;
    int c = d >> 8, ph = (d >> 4) & 15, pw = d & 15;
    int gh = l >> 4, gw = l & 15;
    float v = x[(((b * 4 + c) * 256 + gh * 16 + ph) << 8) + gw * 16 + pw];
    __nv_bfloat16 h = __float2bfloat16(v);
    H[o] = h;
    L[o] = __float2bfloat16(v - __bfloat162float(h));
}

// ---------------- unpatchify ------------------------------------------------
__global__ void unpatchify_kernel(const float* __restrict__ hf, float* __restrict__ out) {
    int o = blockIdx.x * blockDim.x + threadIdx.x;
    if (o >= MROWS * DMODEL) return;
    int W = o & 255, H = (o >> 8) & 255, c = (o >> 16) & 3, b = o >> 18;
    int gh = H >> 4, ph = H & 15, gw = W >> 4, pw = W & 15;
    out[o] = hf[((b * 256 + gh * 16 + gw) << 10) + c * 256 + ph * 16 + pw];
}

// ---------------- LayerNorm + modulate (bf16-split or fp32 out) -------------
template <int BF>
__global__ void ln_mod_kernel(const float* __restrict__ X, const float* __restrict__ s_ptr,
                              const float* __restrict__ b_ptr, int mstride,
                              float* __restrict__ Yf, __nv_bfloat16* __restrict__ Yh,
                              __nv_bfloat16* __restrict__ Yl) {
    const int row = blockIdx.x;
    const int b = row >> 8;
    const int tid = threadIdx.x;
    const float* xr = X + (size_t)row * DMODEL;

    float4 v = *(const float4*)&xr[tid * 4];
    float s = v.x + v.y + v.z + v.w;
    float ss = v.x * v.x + v.y * v.y + v.z * v.z + v.w * v.w;
#pragma unroll
    for (int o = 16; o > 0; o >>= 1) {
        s += __shfl_down_sync(0xffffffffu, s, o);
        ss += __shfl_down_sync(0xffffffffu, ss, o);
    }
    __shared__ float rs[8], rss[8], stats[2];
    int wid = tid >> 5, lane = tid & 31;
    if (lane == 0) { rs[wid] = s; rss[wid] = ss; }
    __syncthreads();
    if (tid == 0) {
        float S = 0.0f, SS = 0.0f;
#pragma unroll
        for (int ww = 0; ww < 8; ww++) { S += rs[ww]; SS += rss[ww]; }
        float mean = S * (1.0f / DMODEL);
        float var = SS * (1.0f / DMODEL) - mean * mean;
        stats[0] = mean;
        stats[1] = rsqrtf(var + 1e-5f);
    }
    __syncthreads();
    float mean = stats[0], rstd = stats[1];
    const float* sp = s_ptr + (size_t)b * mstride;
    const float* bp = b_ptr + (size_t)b * mstride;
    float xv[4] = {v.x, v.y, v.z, v.w};
    float ov[4];
#pragma unroll
    for (int j = 0; j < 4; j++) {
        int col = tid * 4 + j;
        ov[j] = (xv[j] - mean) * rstd * (1.0f + sp[col]) + bp[col];
    }
    size_t base = (size_t)row * DMODEL + tid * 4;
    if (BF) {
        store4_hl(Yh, Yl, base, ov[0], ov[1], ov[2], ov[3]);
    } else {
        *(float4*)&Yf[base] = make_float4(ov[0], ov[1], ov[2], ov[3]);
    }
}

// ---------------- attention (fp32 SIMT, bf16-split output) ------------------
__global__ void attn_kernel(const float* __restrict__ qkv, __nv_bfloat16* __restrict__ OH,
                            __nv_bfloat16* __restrict__ OL) {
    extern __shared__ float sm[];
    float* Ks = sm;
    float* Vs = sm + 256 * 64;
    const int bh = blockIdx.x;
    const int b = bh >> 4, h = bh & 15;
    const int tid = threadIdx.x;
    const float* base = qkv + (size_t)b * LSEQ * 3 * DMODEL;
#pragma unroll
    for (int it = 0; it < 16; it++) {
        int idx = it * 256 + tid;
        int row = idx >> 4;
        int dc = (idx & 15) * 4;
        *(float4*)&Ks[row * 64 + dc] =
            *(const float4*)&base[(size_t)row * 3072 + DMODEL + h * 64 + dc];
        *(float4*)&Vs[row * 64 + dc] =
            *(const float4*)&base[(size_t)row * 3072 + 2 * DMODEL + h * 64 + dc];
    }
    __syncthreads();
    const int i = tid;
    float q[HDIM];
#pragma unroll
    for (int d = 0; d < HDIM; d += 4) {
        float4 t = *(const float4*)&base[(size_t)i * 3072 + h * 64 + d];
        q[d] = t.x; q[d + 1] = t.y; q[d + 2] = t.z; q[d + 3] = t.w;
    }
    float m = -1e30f, ssum = 0.0f;
    float o[HDIM];
#pragma unroll
    for (int d = 0; d < HDIM; d++) o[d] = 0.0f;
    for (int j = 0; j < LSEQ; j++) {
        const float* kj = &Ks[j * 64];
        float sc = 0.0f;
#pragma unroll
        for (int d = 0; d < HDIM; d++) sc = fmaf(q[d], kj[d], sc);
        sc *= 0.125f;
        float nm = fmaxf(m, sc);
        float f = __expf(m - nm);
        float p = __expf(sc - nm);
        ssum = ssum * f + p;
        const float* vj = &Vs[j * 64];
#pragma unroll
        for (int d = 0; d < HDIM; d++) o[d] = fmaf(o[d], f, p * vj[d]);
        m = nm;
    }
    float inv = 1.0f / ssum;
    size_t ob = (size_t)(b * LSEQ + i) * DMODEL + h * 64;
#pragma unroll
    for (int d = 0; d < HDIM; d += 4)
        store4_hl(OH, OL, ob + d, o[d] * inv, o[d + 1] * inv, o[d + 2] * inv, o[d + 3] * inv);
}

// ---------------- small GEMM: C[32,N] = A[32,K=1024] @ B[K,N] ---------------
__global__ void small_gemm(const float* __restrict__ A, const float* __restrict__ B,
                           const float* __restrict__ bias, float* __restrict__ C,
                           int N, int mode) {
    int g = blockIdx.x * 256 + threadIdx.x;   // g = r*N + c
    int r = g / N;
    int c = g - r * N;
    const float* Ar = A + (size_t)r * DMODEL;
    float a0 = 0.f, a1 = 0.f, a2 = 0.f, a3 = 0.f;
    for (int k = 0; k < DMODEL; k += 4) {
        a0 = fmaf(Ar[k + 0], B[(size_t)(k + 0) * N + c], a0);
        a1 = fmaf(Ar[k + 1], B[(size_t)(k + 1) * N + c], a1);
        a2 = fmaf(Ar[k + 2], B[(size_t)(k + 2) * N + c], a2);
        a3 = fmaf(Ar[k + 3], B[(size_t)(k + 3) * N + c], a3);
    }
    float v = a0 + a1 + a2 + a3 + bias[c];
    if (mode == 1) v = silu_f(v);
    C[g] = v;
}

// ---------------- timestep embedding + cond ---------------------------------
__global__ void te_kernel(const int* __restrict__ t, float* __restrict__ te) {
    int idx = blockIdx.x * blockDim.x + threadIdx.x;
    if (idx >= BATCH * DMODEL) return;
    int b = idx >> 10, d = idx & 1023;
    int i = (d < 512) ? d : d - 512;
    float ang = powf(10000.0f, -((float)i) / 512.0f);
    float a = (float)t[b] * ang;
    te[idx] = (d < 512) ? sinf(a) : cosf(a);
}
__global__ void cond_kernel(const int* __restrict__ y, const float* __restrict__ ytab,
                            const float* __restrict__ temb, float* __restrict__ cond,
                            float* __restrict__ scond) {
    int idx = blockIdx.x * blockDim.x + threadIdx.x;
    if (idx >= BATCH * DMODEL) return;
    int b = idx >> 10, d = idx & 1023;
    float c = ytab[(size_t)y[b] * DMODEL + d] + temb[idx];
    cond[idx] = c;
    scond[idx] = silu_f(c);
}

// ---------------- launch ----------------------------------------------------
extern "C" void kernel_launch(void* const* d_in, const int* in_sizes, int n_in,
                              void* d_out, int out_size) {
    const float* x       = (const float*)d_in[0];
    const int*   y       = (const int*)d_in[1];
    const int*   t       = (const int*)d_in[2];
    const float* xw      = (const float*)d_in[3];
    const float* xb      = (const float*)d_in[4];
    const float* ytab    = (const float*)d_in[6];
    const float* t_w1    = (const float*)d_in[7];
    const float* t_b1    = (const float*)d_in[8];
    const float* t_w2    = (const float*)d_in[9];
    const float* t_b2    = (const float*)d_in[10];
    const float* qkv_w   = (const float*)d_in[11];
    const float* qkv_b   = (const float*)d_in[12];
    const float* proj_w  = (const float*)d_in[13];
    const float* proj_b  = (const float*)d_in[14];
    const float* mlp_w1  = (const float*)d_in[15];
    const float* mlp_b1  = (const float*)d_in[16];
    const float* mlp_w2  = (const float*)d_in[17];
    const float* mlp_b2  = (const float*)d_in[18];
    const float* cond_w  = (const float*)d_in[19];
    const float* cond_b  = (const float*)d_in[20];
    const float* final_w = (const float*)d_in[21];
    const float* final_b = (const float*)d_in[22];
    float* outp = (float*)d_out;

    __nv_bfloat16 *XpH, *XpL, *tH, *tL, *aH, *aL, *hidH, *hidL;
    __nv_bfloat16 *WeH, *WeL, *WqH, *WqL, *WpH, *WpL, *W1H, *W1L, *W2H, *W2L;
    float *h, *qkvb, *te, *t1, *temb, *cond, *scond, *mods, *fmods;
    cudaGetSymbolAddress((void**)&XpH, g_XpH);  cudaGetSymbolAddress((void**)&XpL, g_XpL);
    cudaGetSymbolAddress((void**)&h, g_h);
    cudaGetSymbolAddress((void**)&tH, g_tH);    cudaGetSymbolAddress((void**)&tL, g_tL);
    cudaGetSymbolAddress((void**)&qkvb, g_qkv);
    cudaGetSymbolAddress((void**)&aH, g_aH);    cudaGetSymbolAddress((void**)&aL, g_aL);
    cudaGetSymbolAddress((void**)&hidH, g_hidH); cudaGetSymbolAddress((void**)&hidL, g_hidL);
    cudaGetSymbolAddress((void**)&WeH, g_WeH);  cudaGetSymbolAddress((void**)&WeL, g_WeL);
    cudaGetSymbolAddress((void**)&WqH, g_WqH);  cudaGetSymbolAddress((void**)&WqL, g_WqL);
    cudaGetSymbolAddress((void**)&WpH, g_WpH);  cudaGetSymbolAddress((void**)&WpL, g_WpL);
    cudaGetSymbolAddress((void**)&W1H, g_W1H);  cudaGetSymbolAddress((void**)&W1L, g_W1L);
    cudaGetSymbolAddress((void**)&W2H, g_W2H);  cudaGetSymbolAddress((void**)&W2L, g_W2L);
    cudaGetSymbolAddress((void**)&te, g_te);    cudaGetSymbolAddress((void**)&t1, g_t1);
    cudaGetSymbolAddress((void**)&temb, g_temb);
    cudaGetSymbolAddress((void**)&cond, g_cond); cudaGetSymbolAddress((void**)&scond, g_scond);
    cudaGetSymbolAddress((void**)&mods, g_mods); cudaGetSymbolAddress((void**)&fmods, g_fmods);

    cudaFuncSetAttribute(attn_kernel, cudaFuncAttributeMaxDynamicSharedMemorySize, 131072);
    cudaFuncSetAttribute(gemm_mma<0>, cudaFuncAttributeMaxDynamicSharedMemorySize, GEMM_SMEM);
    cudaFuncSetAttribute(gemm_mma<1>, cudaFuncAttributeMaxDynamicSharedMemorySize, GEMM_SMEM);
    cudaFuncSetAttribute(gemm_mma<2>, cudaFuncAttributeMaxDynamicSharedMemorySize, GEMM_SMEM);

    const int D = DMODEL;
    dim3 tb32(32, 8);

    // stem
    patchify_kernel<<<(MROWS * D) / 256, 256>>>(x, XpH, XpL);
    transpose_split<<<dim3(D / 32, D / 32), tb32>>>(xw, WeH, WeL, D, D);
    gemm_mma<0><<<dim3(D / 128, MROWS / 128), 256, GEMM_SMEM>>>(
        XpH, XpL, WeH, WeL, xb, h, nullptr, nullptr, nullptr, nullptr, 0, D, D);

    // cond path
    te_kernel<<<(BATCH * D) / 256, 256>>>(t, te);
    small_gemm<<<(32 * D) / 256, 256>>>(te, t_w1, t_b1, t1, D, 1);
    small_gemm<<<(32 * D) / 256, 256>>>(t1, t_w2, t_b2, temb, D, 0);
    cond_kernel<<<(BATCH * D) / 256, 256>>>(y, ytab, temb, cond, scond);

    for (int l = 0; l < NLAYERS; l++) {
        const float* cwl = cond_w + (size_t)l * D * 6 * D;
        const float* cbl = cond_b + (size_t)l * 6 * D;
        const float* qwl = qkv_w + (size_t)l * D * 3 * D;
        const float* qbl = qkv_b + (size_t)l * 3 * D;
        const float* pwl = proj_w + (size_t)l * D * D;
        const float* pbl = proj_b + (size_t)l * D;
        const float* w1l = mlp_w1 + (size_t)l * D * 4 * D;
        const float* b1l = mlp_b1 + (size_t)l * 4 * D;
        const float* w2l = mlp_w2 + (size_t)l * 4 * D * D;
        const float* b2l = mlp_b2 + (size_t)l * D;

        // weight prep (transposed + split)
        transpose_split<<<dim3((3 * D) / 32, D / 32), tb32>>>(qwl, WqH, WqL, D, 3 * D);
        transpose_split<<<dim3(D / 32, D / 32), tb32>>>(pwl, WpH, WpL, D, D);
        transpose_split<<<dim3((4 * D) / 32, D / 32), tb32>>>(w1l, W1H, W1L, D, 4 * D);
        transpose_split<<<dim3(D / 32, (4 * D) / 32), tb32>>>(w2l, W2H, W2L, 4 * D, D);

        small_gemm<<<(32 * 6 * D) / 256, 256>>>(scond, cwl, cbl, mods, 6 * D, 0);

        // attention branch
        ln_mod_kernel<1><<<MROWS, 256>>>(h, mods + 0, mods + D, 6 * D, nullptr, tH, tL);
        gemm_mma<0><<<dim3((3 * D) / 128, MROWS / 128), 256, GEMM_SMEM>>>(
            tH, tL, WqH, WqL, qbl, qkvb, nullptr, nullptr, nullptr, nullptr, 0, 3 * D, D);
        attn_kernel<<<BATCH * NHEADS, 256, 131072>>>(qkvb, aH, aL);
        gemm_mma<2><<<dim3(D / 128, MROWS / 128), 256, GEMM_SMEM>>>(
            aH, aL, WpH, WpL, pbl, h, nullptr, nullptr, h, mods + 2 * D, 6 * D, D, D);

        // mlp branch
        ln_mod_kernel<1><<<MROWS, 256>>>(h, mods + 3 * D, mods + 4 * D, 6 * D, nullptr, tH, tL);
        gemm_mma<1><<<dim3((4 * D) / 128, MROWS / 128), 256, GEMM_SMEM>>>(
            tH, tL, W1H, W1L, b1l, nullptr, hidH, hidL, nullptr, nullptr, 0, 4 * D, D);
        gemm_mma<2><<<dim3(D / 128, MROWS / 128), 256, GEMM_SMEM>>>(
            hidH, hidL, W2H, W2L, b2l, h, nullptr, nullptr, h, mods + 5 * D, 6 * D, D, 4 * D);
    }

    // final modulation + unpatchify (reuse qkv buffer as fp32 scratch)
    small_gemm<<<(32 * 2 * D) / 256, 256>>>(cond, final_w, final_b, fmods, 2 * D, 0);
    ln_mod_kernel<0><<<MROWS, 256>>>(h, fmods + 0, fmods + D, 2 * D, qkvb, nullptr, nullptr);
    unpatchify_kernel<<<(MROWS * D) / 256, 256>>>(qkvb, outp);
}